// round 4
// baseline (speedup 1.0000x reference)
#include <cuda_runtime.h>
#include <cuda_bf16.h>
#include <cstdint>

// DistortionLoss, O(N) per row, fully telescoped and T-deferred:
//   loss = inv * [ T*sum_e g_e*P_e  -  sum_e g_e*P_e^2  +  (1/3)*sum_i w_i^2*dz_i ]
//   g_e = z_{e+1}-z_{e-1}, P_e = exclusive prefix of w, T = total w,
//   inv = 1/(far-near).
// Boundary handling: e=0 term has P_0 = 0, so z_{-1} may be garbage (clamped).
//
// One warp per row, 4 elements per lane. All z neighbors loaded directly
// (same cache lines) instead of shuffled -> shorter dependent chain.

#define FULL 0xffffffffu

__global__ __launch_bounds__(256)
void distortion_loss_kernel(const float* __restrict__ w,
                            const float* __restrict__ z,
                            const float* __restrict__ nearv,
                            const float* __restrict__ farv,
                            float* __restrict__ out,
                            int R)
{
    const int row  = (blockIdx.x * blockDim.x + threadIdx.x) >> 5;
    const int lane = threadIdx.x & 31;
    if (row >= R) return;

    const float* wr = w + (size_t)row * 128;
    const float* zr = z + (size_t)row * 129;

    // ---- loads, all independent (max MLP, no cross-lane deps) ----
    const float4 w4 = reinterpret_cast<const float4*>(wr)[lane];

    const int zi = lane * 4;
    const float zm1 = __ldg(&zr[(zi == 0) ? 0 : zi - 1]);  // killed by P0=0 at lane 0
    const float z0  = __ldg(&zr[zi + 0]);
    const float z1  = __ldg(&zr[zi + 1]);
    const float z2  = __ldg(&zr[zi + 2]);
    const float z3  = __ldg(&zr[zi + 3]);
    const float z4  = __ldg(&zr[zi + 4]);                  // valid: max index 128

    const float nr = __ldg(&nearv[row]);
    const float fr = __ldg(&farv[row]);

    // ---- lane-local w prefixes ----
    const float pre1 = w4.x;
    const float pre2 = pre1 + w4.y;
    const float pre3 = pre2 + w4.z;
    const float wc   = pre3 + w4.w;

    // ---- warp inclusive scan of lane totals ----
    float wInc = wc;
#pragma unroll
    for (int o = 1; o < 32; o <<= 1) {
        float t = __shfl_up_sync(FULL, wInc, o);
        if (lane >= o) wInc += t;
    }
    const float Wex = wInc - wc;                      // exclusive lane prefix
    const float T   = __shfl_sync(FULL, wInc, 31);    // row total (overlaps below)

    // ---- gaps (independent of scan; computed in parallel with it) ----
    const float g0 = z1 - zm1;
    const float g1 = z2 - z0;
    const float g2 = z3 - z1;
    const float g3 = z4 - z2;

    const float P0 = Wex;
    const float P1 = Wex + pre1;
    const float P2 = Wex + pre2;
    const float P3 = Wex + pre3;

    // A = sum g*P ; C = (1/3)*sum w^2*dz - sum g*P^2
    const float t0 = g0 * P0;
    const float t1 = g1 * P1;
    const float t2 = g2 * P2;
    const float t3 = g3 * P3;

    float A = (t0 + t1) + (t2 + t3);

    float C;
    C =       (w4.x * w4.x) * (z1 - z0);
    C = fmaf( (w4.y * w4.y), (z2 - z1), C);
    C = fmaf( (w4.z * w4.z), (z3 - z2), C);
    C = fmaf( (w4.w * w4.w), (z4 - z3), C);
    C *= (1.0f / 3.0f);
    C = fmaf(-t0, P0, C);
    C = fmaf(-t1, P1, C);
    C = fmaf(-t2, P2, C);
    C = fmaf(-t3, P3, C);

    // ---- interleaved independent butterflies for A and C ----
#pragma unroll
    for (int o = 16; o > 0; o >>= 1) {
        A += __shfl_xor_sync(FULL, A, o);
        C += __shfl_xor_sync(FULL, C, o);
    }

    if (lane == 0)
        out[row] = fmaf(T, A, C) * __fdividef(1.0f, fr - nr);
}

extern "C" void kernel_launch(void* const* d_in, const int* in_sizes, int n_in,
                              void* d_out, int out_size)
{
    const float* w  = (const float*)d_in[0];   // (R, 128, 1)
    const float* z  = (const float*)d_in[1];   // (R, 129)
    const float* nr = (const float*)d_in[2];   // (R, 1)
    const float* fr = (const float*)d_in[3];   // (R, 1)
    float* out = (float*)d_out;                // (R, 1)

    const int R = in_sizes[0] / 128;
    const int threads = 256;                   // 8 warps = 8 rows per block
    const int blocks  = (R * 32 + threads - 1) / threads;
    distortion_loss_kernel<<<blocks, threads>>>(w, z, nr, fr, out, R);
}